// round 15
// baseline (speedup 1.0000x reference)
#include <cuda_runtime.h>
#include <cuda_bf16.h>
#include <cstdint>
#include <math.h>

#define BB 4096
#define LL 50
#define DD 64

constexpr int ROWS_TOT = BB * LL;        // 204800
constexpr int NT16     = ROWS_TOT / 16;  // 12800 warp-tiles
constexpr int THR      = 256;

// ---- mlp smem layout (bytes): hi-only paired-fragment tiles, all K=64 ----
constexpr int L_GV1  = 0;                // 8192 each
constexpr int L_GV2  = 8192;
constexpr int L_GV3  = 16384;
constexpr int L_ATT1 = 24576;            // fjt half only (K=64) — q half via qc
constexpr int L_ATT2 = 32768;
constexpr int FBASE  = 40960;
constexpr int F_BG1 = 0, F_BG2 = 64, F_BG3 = 128, F_BA1 = 192, F_BA2 = 256;
constexpr int F_W3 = 320, F_BA3 = 384, F_ER = 448;
constexpr int SMEM_SZ = FBASE + 768 * 4;   // 44032 B

// device scratch
__device__ float g_scores[ROWS_TOT];
__device__ float g_fjt[ROWS_TOT * DD];
__device__ float g_zq[BB * 128];
__device__ float g_qc[BB * DD];

// ===================== helpers =====================
__device__ __forceinline__ uint32_t cvt2(float v_lo, float v_hi) {
    uint32_t r;
    asm("cvt.rn.bf16x2.f32 %0, %1, %2;" : "=r"(r) : "f"(v_hi), "f"(v_lo));
    return r;
}
__device__ __forceinline__ void mma(float* d, const uint32_t* a, uint32_t b0, uint32_t b1) {
    asm volatile(
        "mma.sync.aligned.m16n8k16.row.col.f32.bf16.bf16.f32 "
        "{%0,%1,%2,%3}, {%4,%5,%6,%7}, {%8,%9}, {%0,%1,%2,%3};"
        : "+f"(d[0]), "+f"(d[1]), "+f"(d[2]), "+f"(d[3])
        : "r"(a[0]), "r"(a[1]), "r"(a[2]), "r"(a[3]), "r"(b0), "r"(b1));
}

// K=64 single-pass bf16, paired fragments: one LDS.128 per (kt, nt-pair)
__device__ __forceinline__ void run_1p(const char* base,
        const uint32_t (&A)[4][4], float (&D)[8][4]) {
#pragma unroll
    for (int nt = 0; nt < 8; nt++) { D[nt][0] = 0.f; D[nt][1] = 0.f; D[nt][2] = 0.f; D[nt][3] = 0.f; }
#pragma unroll
    for (int kt = 0; kt < 4; kt++) {
#pragma unroll
        for (int ntp = 0; ntp < 4; ntp++) {
            uint4 bv = *reinterpret_cast<const uint4*>(base + (kt * 4 + ntp) * 512);
            mma(D[ntp * 2],     A[kt], bv.x, bv.y);
            mma(D[ntp * 2 + 1], A[kt], bv.z, bv.w);
        }
    }
}

// bias (+extra per-row) (+relu) (+gmem store), D -> next A frags (bf16)
template<bool RELU, bool EX, bool SG>
__device__ __forceinline__ void epilogue(float (&D)[8][4], uint32_t (&A)[4][4],
        const float* bias, const float* e0, const float* e1, float* g0, float* g1, int tig) {
#pragma unroll
    for (int nt = 0; nt < 8; nt++) {
        int col = nt * 8 + 2 * tig;
        float2 bc = *reinterpret_cast<const float2*>(bias + col);
        float v0 = D[nt][0] + bc.x, v1 = D[nt][1] + bc.y;
        float v2 = D[nt][2] + bc.x, v3 = D[nt][3] + bc.y;
        if (EX) {
            float2 ea = *reinterpret_cast<const float2*>(e0 + col);
            float2 eb = *reinterpret_cast<const float2*>(e1 + col);
            v0 += ea.x; v1 += ea.y; v2 += eb.x; v3 += eb.y;
        }
        if (RELU) {
            v0 = fmaxf(v0, 0.f); v1 = fmaxf(v1, 0.f);
            v2 = fmaxf(v2, 0.f); v3 = fmaxf(v3, 0.f);
        }
        if (SG) {
            *reinterpret_cast<float2*>(g0 + col) = make_float2(v0, v1);
            *reinterpret_cast<float2*>(g1 + col) = make_float2(v2, v3);
        }
        int kt = nt >> 1, ix = (nt & 1) * 2;
        A[kt][ix]     = cvt2(v0, v1);
        A[kt][ix + 1] = cvt2(v2, v3);
    }
}

__device__ __forceinline__ void gather_bf16(const float* p0, const float* p1,
        uint32_t (&A)[4][4]) {
#pragma unroll
    for (int kt = 0; kt < 4; kt++) {
        float2 x0 = *reinterpret_cast<const float2*>(p0 + kt * 16);
        float2 x1 = *reinterpret_cast<const float2*>(p1 + kt * 16);
        float2 x2 = *reinterpret_cast<const float2*>(p0 + kt * 16 + 8);
        float2 x3 = *reinterpret_cast<const float2*>(p1 + kt * 16 + 8);
        A[kt][0] = cvt2(x0.x, x0.y);
        A[kt][1] = cvt2(x1.x, x1.y);
        A[kt][2] = cvt2(x2.x, x2.y);
        A[kt][3] = cvt2(x3.x, x3.y);
    }
}

// hi-only packing in PAIRED fragment layout:
// block(kt, ntp) = 512B; thread th holds 16B = frags of nt=2*ntp and nt=2*ntp+1
__device__ __forceinline__ void pack_tile_hi(char* dh, const float* __restrict__ w,
                                             int KT, int tid) {
    for (int e = tid; e < KT * 4 * 32; e += THR) {
        int kt = e >> 7, rem = e & 127, ntp = rem >> 5, th = rem & 31;
        int tg = th & 3, gn = th >> 2;
        int k0 = kt * 16 + tg * 2;
        uint32_t v[4];
#pragma unroll
        for (int h = 0; h < 2; h++) {
            int n = (ntp * 2 + h) * 8 + gn;
            v[2 * h]     = cvt2(w[k0 * 64 + n],       w[(k0 + 1) * 64 + n]);
            v[2 * h + 1] = cvt2(w[(k0 + 8) * 64 + n], w[(k0 + 9) * 64 + n]);
        }
        *reinterpret_cast<uint4*>(dh + (kt * 4 + ntp) * 512 + th * 16) =
            make_uint4(v[0], v[1], v[2], v[3]);
    }
}

// ===================== qc kernel: qc[b] = embed_i[nodes_v[b]] @ att_w1[64:128] =====================
__global__ void __launch_bounds__(256) qc_kernel(
    const int* __restrict__ nodes_v, const float* __restrict__ embed_i,
    const float* __restrict__ att_w1) {
    int j = threadIdx.x & 63;
    int sub = threadIdx.x >> 6;   // 0..3
    for (int b = blockIdx.x * 4 + sub; b < BB; b += gridDim.x * 4) {
        const float* q = embed_i + (size_t)nodes_v[b] * 64;
        float s = 0.f;
#pragma unroll 8
        for (int k = 0; k < 64; k++) s += q[k] * att_w1[(64 + k) * 64 + j];
        g_qc[(size_t)b * 64 + j] = s;
    }
}

// ===================== HMMA MLP kernel =====================
__global__ void __launch_bounds__(THR, 2) mlp_mma_kernel(
    const int* __restrict__ nodes_v,
    const int* __restrict__ neigh_u, const int* __restrict__ neigh_r,
    const float* __restrict__ embed_u,
    const float* __restrict__ embed_r,
    const float* __restrict__ gv_w1, const float* __restrict__ gv_b1,
    const float* __restrict__ gv_w2, const float* __restrict__ gv_b2,
    const float* __restrict__ gv_w3, const float* __restrict__ gv_b3,
    const float* __restrict__ att_w1, const float* __restrict__ att_b1,
    const float* __restrict__ att_w2, const float* __restrict__ att_b2,
    const float* __restrict__ att_w3, const float* __restrict__ att_b3) {
    extern __shared__ char smem[];
    float* smf = reinterpret_cast<float*>(smem + FBASE);
    int tid = threadIdx.x;

    pack_tile_hi(smem + L_GV1, gv_w1, 4, tid);     // pt half rows 0..63
    pack_tile_hi(smem + L_GV2, gv_w2, 4, tid);
    pack_tile_hi(smem + L_GV3, gv_w3, 4, tid);
    pack_tile_hi(smem + L_ATT1, att_w1, 4, tid);   // fjt half rows 0..63
    pack_tile_hi(smem + L_ATT2, att_w2, 4, tid);
    if (tid < 64) {
        smf[F_BG1 + tid] = gv_b1[tid];
        smf[F_BG2 + tid] = gv_b2[tid];
        smf[F_BG3 + tid] = gv_b3[tid];
        smf[F_BA1 + tid] = att_b1[tid];
        smf[F_BA2 + tid] = att_b2[tid];
        smf[F_W3 + tid]  = att_w3[tid];
    }
    for (int e = tid; e < 320; e += THR) {
        int r = e >> 6, j = e & 63;
        float s = 0.f;
#pragma unroll 8
        for (int k = 0; k < 64; k++) s += embed_r[r * 64 + k] * gv_w1[(64 + k) * 64 + j];
        smf[F_ER + e] = s;
    }
    if (tid == 0) smf[F_BA3] = att_b3[0];
    __syncthreads();

    const char* ws = smem;
    int lane = tid & 31;
    int tig = lane & 3, gid = lane >> 2;
    int gw = blockIdx.x * (THR / 32) + (tid >> 5);
    int stride = gridDim.x * (THR / 32);
    int lb = lane * 16;

    uint32_t Ahi[4][4];
    float D[8][4];

    for (int t = gw; t < NT16; t += stride) {
        int grow0 = t * 16 + gid, grow1 = grow0 + 8;
        int nu0 = neigh_u[grow0], nu1 = neigh_u[grow1];
        int nr0 = neigh_r[grow0], nr1 = neigh_r[grow1];
        int b0 = (int)((unsigned)grow0 / 50u), b1 = (int)((unsigned)grow1 / 50u);

        gather_bf16(embed_u + (size_t)nu0 * 64 + 2 * tig,
                    embed_u + (size_t)nu1 * 64 + 2 * tig, Ahi);

        // L1: gv1(pt half) + er_proj + bg1, relu
        run_1p(ws + L_GV1 + lb, Ahi, D);
        epilogue<true, true, false>(D, Ahi, smf + F_BG1,
                                    smf + F_ER + nr0 * 64, smf + F_ER + nr1 * 64,
                                    nullptr, nullptr, tig);
        // L2: gv2 + bg2, relu
        run_1p(ws + L_GV2 + lb, Ahi, D);
        epilogue<true, false, false>(D, Ahi, smf + F_BG2,
                                     nullptr, nullptr, nullptr, nullptr, tig);
        // L3: gv3 + bg3 -> fjt (gmem) + A
        run_1p(ws + L_GV3 + lb, Ahi, D);
        epilogue<false, false, true>(D, Ahi, smf + F_BG3,
                                     nullptr, nullptr,
                                     g_fjt + (size_t)grow0 * 64, g_fjt + (size_t)grow1 * 64, tig);

        // L4: att1 fjt-half (K=64) + qc[b] (fp32, precomputed) + ba1, relu
        run_1p(ws + L_ATT1 + lb, Ahi, D);
        epilogue<true, true, false>(D, Ahi, smf + F_BA1,
                                    g_qc + (size_t)b0 * 64, g_qc + (size_t)b1 * 64,
                                    nullptr, nullptr, tig);
        // L5: att2 + score dot
        run_1p(ws + L_ATT2 + lb, Ahi, D);
        {
            float s0 = 0.f, s1 = 0.f;
            float ba3v = smf[F_BA3];
#pragma unroll
            for (int nt = 0; nt < 8; nt++) {
                int col = nt * 8 + 2 * tig;
                float2 bc = *reinterpret_cast<const float2*>(smf + F_BA2 + col);
                float2 wc = *reinterpret_cast<const float2*>(smf + F_W3 + col);
                s0 += fmaxf(D[nt][0] + bc.x, 0.f) * wc.x + fmaxf(D[nt][1] + bc.y, 0.f) * wc.y;
                s1 += fmaxf(D[nt][2] + bc.x, 0.f) * wc.x + fmaxf(D[nt][3] + bc.y, 0.f) * wc.y;
            }
            s0 += __shfl_xor_sync(0xffffffffu, s0, 1);
            s0 += __shfl_xor_sync(0xffffffffu, s0, 2);
            s1 += __shfl_xor_sync(0xffffffffu, s1, 1);
            s1 += __shfl_xor_sync(0xffffffffu, s1, 2);
            if (tig == 0) {
                g_scores[grow0] = s0 + ba3v;
                g_scores[grow1] = s1 + ba3v;
            }
        }
    }
}

// ===================== agg kernel =====================
__global__ void __launch_bounds__(256) agg_kernel(
    const int* __restrict__ nodes_v, const float* __restrict__ embed_i) {
    __shared__ float mus[8][64];
    int tid = threadIdx.x;
    int warp = tid >> 5, lane = tid & 31;
    int b = blockIdx.x * 8 + warp;

    float s0 = (lane < LL) ? g_scores[b * LL + lane] : -1e30f;
    float s1 = (lane + 32 < LL) ? g_scores[b * LL + lane + 32] : -1e30f;
    float mx = fmaxf(s0, s1);
#pragma unroll
    for (int o = 16; o > 0; o >>= 1) mx = fmaxf(mx, __shfl_xor_sync(0xffffffffu, mx, o));
    float e0 = (lane < LL) ? __expf(s0 - mx) : 0.f;
    float e1 = (lane + 32 < LL) ? __expf(s1 - mx) : 0.f;
    float den = e0 + e1;
#pragma unroll
    for (int o = 16; o > 0; o >>= 1) den += __shfl_xor_sync(0xffffffffu, den, o);
    mus[warp][lane] = e0;
    mus[warp][lane + 32] = e1;
    __syncwarp();

    float a0 = 0.f, a1 = 0.f;
    const float* fb = g_fjt + (size_t)b * LL * 64 + 2 * lane;
#pragma unroll 10
    for (int l = 0; l < LL; l++) {
        float m = mus[warp][l];
        float2 v = *reinterpret_cast<const float2*>(fb + l * 64);
        a0 += m * v.x;
        a1 += m * v.y;
    }
    float inv = 1.f / den;
    float* zb = g_zq + (size_t)b * 128;
    *reinterpret_cast<float2*>(zb + 2 * lane) = make_float2(a0 * inv, a1 * inv);
    float2 qv = *reinterpret_cast<const float2*>(embed_i + (size_t)nodes_v[b] * 64 + 2 * lane);
    *reinterpret_cast<float2*>(zb + 64 + 2 * lane) = qv;
}

// ===================== mlp2 kernel =====================
__global__ void __launch_bounds__(256) mlp2_kernel(
    const float* __restrict__ wr1_w, const float* __restrict__ wr1_b,
    const float* __restrict__ wr2_w, const float* __restrict__ wr2_b,
    float* __restrict__ out) {
    __shared__ float w1s[128 * 64];
    __shared__ float w2s[64 * 64];
    __shared__ float b1s[64], b2s[64];
    __shared__ float zqs[8][128];
    __shared__ float zzs[8][64];

    int tid = threadIdx.x;
    int warp = tid >> 5, lane = tid & 31;

    {
        const float4* s1 = reinterpret_cast<const float4*>(wr1_w);
        float4* d1 = reinterpret_cast<float4*>(w1s);
        for (int e = tid; e < 128 * 16; e += 256) d1[e] = s1[e];
        const float4* s2 = reinterpret_cast<const float4*>(wr2_w);
        float4* d2 = reinterpret_cast<float4*>(w2s);
        for (int e = tid; e < 64 * 16; e += 256) d2[e] = s2[e];
        if (tid < 64) { b1s[tid] = wr1_b[tid]; b2s[tid] = wr2_b[tid]; }
    }
    __syncthreads();

#pragma unroll
    for (int i = 0; i < 2; i++) {
        int b = blockIdx.x * 16 + warp * 2 + i;

        *reinterpret_cast<float4*>(&zqs[warp][lane * 4]) =
            *reinterpret_cast<const float4*>(g_zq + (size_t)b * 128 + lane * 4);
        __syncwarp();

        float o0 = b1s[lane], o1 = b1s[lane + 32];
#pragma unroll 16
        for (int k = 0; k < 128; k++) {
            float v = zqs[warp][k];
            o0 += v * w1s[k * 64 + lane];
            o1 += v * w1s[k * 64 + lane + 32];
        }
        zzs[warp][lane]      = fmaxf(o0, 0.f);
        zzs[warp][lane + 32] = fmaxf(o1, 0.f);
        __syncwarp();

        float p0 = b2s[lane], p1 = b2s[lane + 32];
#pragma unroll 16
        for (int k = 0; k < 64; k++) {
            float v = zzs[warp][k];
            p0 += v * w2s[k * 64 + lane];
            p1 += v * w2s[k * 64 + lane + 32];
        }
        out[b * 64 + lane]      = fmaxf(p0, 0.f);
        out[b * 64 + lane + 32] = fmaxf(p1, 0.f);
        __syncwarp();
    }
}

extern "C" void kernel_launch(void* const* d_in, const int* in_sizes, int n_in,
                              void* d_out, int out_size) {
    const int*   nodes_v = (const int*)d_in[0];
    const int*   neigh_u = (const int*)d_in[1];
    const int*   neigh_r = (const int*)d_in[2];
    const float* embed_u = (const float*)d_in[3];
    const float* embed_i = (const float*)d_in[4];
    const float* embed_r = (const float*)d_in[5];
    const float* gv_w1  = (const float*)d_in[6];
    const float* gv_b1  = (const float*)d_in[7];
    const float* gv_w2  = (const float*)d_in[8];
    const float* gv_b2  = (const float*)d_in[9];
    const float* gv_w3  = (const float*)d_in[10];
    const float* gv_b3  = (const float*)d_in[11];
    const float* att_w1 = (const float*)d_in[12];
    const float* att_b1 = (const float*)d_in[13];
    const float* att_w2 = (const float*)d_in[14];
    const float* att_b2 = (const float*)d_in[15];
    const float* att_w3 = (const float*)d_in[16];
    const float* att_b3 = (const float*)d_in[17];
    const float* wr1_w  = (const float*)d_in[18];
    const float* wr1_b  = (const float*)d_in[19];
    const float* wr2_w  = (const float*)d_in[20];
    const float* wr2_b  = (const float*)d_in[21];
    float* out = (float*)d_out;

    cudaFuncSetAttribute(mlp_mma_kernel, cudaFuncAttributeMaxDynamicSharedMemorySize, SMEM_SZ);

    int smCount = 148;
    cudaDeviceGetAttribute(&smCount, cudaDevAttrMultiProcessorCount, 0);

    qc_kernel<<<128, 256>>>(nodes_v, embed_i, att_w1);

    mlp_mma_kernel<<<2 * smCount, THR, SMEM_SZ>>>(
        nodes_v, neigh_u, neigh_r, embed_u, embed_r,
        gv_w1, gv_b1, gv_w2, gv_b2, gv_w3, gv_b3,
        att_w1, att_b1, att_w2, att_b2, att_w3, att_b3);

    agg_kernel<<<BB / 8, 256>>>(nodes_v, embed_i);

    mlp2_kernel<<<BB / 16, 256>>>(wr1_w, wr1_b, wr2_w, wr2_b, out);
}

// round 16
// speedup vs baseline: 1.1586x; 1.1586x over previous
#include <cuda_runtime.h>
#include <cuda_bf16.h>
#include <cstdint>
#include <math.h>

#define BB 4096
#define LL 50
#define DD 64

constexpr int ROWS_TOT = BB * LL;        // 204800
constexpr int NT16     = ROWS_TOT / 16;  // 12800 warp-tiles
constexpr int THR      = 256;

// ---- mlp smem layout (bytes): hi-only PAIRED-fragment tiles ----
constexpr int L_GV1  = 0;                // 8192
constexpr int L_GV2  = 8192;
constexpr int L_GV3  = 16384;
constexpr int L_ATT1 = 24576;            // 16384 (K=128)
constexpr int L_ATT2 = 40960;            // 8192
constexpr int FBASE  = 49152;
constexpr int F_BG1 = 0, F_BG2 = 64, F_BG3 = 128, F_BA1 = 192, F_BA2 = 256;
constexpr int F_W3 = 320, F_BA3 = 384, F_ER = 448;
constexpr int SMEM_SZ = FBASE + 768 * 4;   // 52224 B

// device scratch
__device__ float g_scores[ROWS_TOT];
__device__ float g_fjt[ROWS_TOT * DD];
__device__ float g_zq[BB * 128];

// ===================== helpers =====================
__device__ __forceinline__ uint32_t cvt2(float v_lo, float v_hi) {
    uint32_t r;
    asm("cvt.rn.bf16x2.f32 %0, %1, %2;" : "=r"(r) : "f"(v_hi), "f"(v_lo));
    return r;
}
__device__ __forceinline__ void mma(float* d, const uint32_t* a, uint32_t b0, uint32_t b1) {
    asm volatile(
        "mma.sync.aligned.m16n8k16.row.col.f32.bf16.bf16.f32 "
        "{%0,%1,%2,%3}, {%4,%5,%6,%7}, {%8,%9}, {%0,%1,%2,%3};"
        : "+f"(d[0]), "+f"(d[1]), "+f"(d[2]), "+f"(d[3])
        : "r"(a[0]), "r"(a[1]), "r"(a[2]), "r"(a[3]), "r"(b0), "r"(b1));
}

// K=64 single-pass bf16, PAIRED fragments: one LDS.128 per (kt, nt-pair)
__device__ __forceinline__ void run_1p(const char* base,
        const uint32_t (&A)[4][4], float (&D)[8][4]) {
#pragma unroll
    for (int nt = 0; nt < 8; nt++) { D[nt][0] = 0.f; D[nt][1] = 0.f; D[nt][2] = 0.f; D[nt][3] = 0.f; }
#pragma unroll
    for (int kt = 0; kt < 4; kt++) {
#pragma unroll
        for (int ntp = 0; ntp < 4; ntp++) {
            uint4 bv = *reinterpret_cast<const uint4*>(base + (kt * 4 + ntp) * 512);
            mma(D[ntp * 2],     A[kt], bv.x, bv.y);
            mma(D[ntp * 2 + 1], A[kt], bv.z, bv.w);
        }
    }
}

// att1: K=128 single-pass, paired; kt 0..3 from Af (fjt), kt 4..7 from Aq
__device__ __forceinline__ void run_att1(const char* base,
        const uint32_t (&Af)[4][4], const uint32_t (&Aq)[4][4], float (&D)[8][4]) {
#pragma unroll
    for (int nt = 0; nt < 8; nt++) { D[nt][0] = 0.f; D[nt][1] = 0.f; D[nt][2] = 0.f; D[nt][3] = 0.f; }
#pragma unroll
    for (int kt = 0; kt < 8; kt++) {
        const uint32_t* Asel = (kt < 4) ? Af[kt] : Aq[kt - 4];
#pragma unroll
        for (int ntp = 0; ntp < 4; ntp++) {
            uint4 bv = *reinterpret_cast<const uint4*>(base + (kt * 4 + ntp) * 512);
            mma(D[ntp * 2],     Asel, bv.x, bv.y);
            mma(D[ntp * 2 + 1], Asel, bv.z, bv.w);
        }
    }
}

// bias (+extra) (+relu) (+gmem store), D -> next A frags (bf16)
template<bool RELU, bool EX, bool SG>
__device__ __forceinline__ void epilogue(float (&D)[8][4], uint32_t (&A)[4][4],
        const float* bias, const float* e0, const float* e1, float* g0, float* g1, int tig) {
#pragma unroll
    for (int nt = 0; nt < 8; nt++) {
        int col = nt * 8 + 2 * tig;
        float2 bc = *reinterpret_cast<const float2*>(bias + col);
        float v0 = D[nt][0] + bc.x, v1 = D[nt][1] + bc.y;
        float v2 = D[nt][2] + bc.x, v3 = D[nt][3] + bc.y;
        if (EX) {
            float2 ea = *reinterpret_cast<const float2*>(e0 + col);
            float2 eb = *reinterpret_cast<const float2*>(e1 + col);
            v0 += ea.x; v1 += ea.y; v2 += eb.x; v3 += eb.y;
        }
        if (RELU) {
            v0 = fmaxf(v0, 0.f); v1 = fmaxf(v1, 0.f);
            v2 = fmaxf(v2, 0.f); v3 = fmaxf(v3, 0.f);
        }
        if (SG) {
            *reinterpret_cast<float2*>(g0 + col) = make_float2(v0, v1);
            *reinterpret_cast<float2*>(g1 + col) = make_float2(v2, v3);
        }
        int kt = nt >> 1, ix = (nt & 1) * 2;
        A[kt][ix]     = cvt2(v0, v1);
        A[kt][ix + 1] = cvt2(v2, v3);
    }
}

__device__ __forceinline__ void gather_bf16(const float* p0, const float* p1,
        uint32_t (&A)[4][4]) {
#pragma unroll
    for (int kt = 0; kt < 4; kt++) {
        float2 x0 = *reinterpret_cast<const float2*>(p0 + kt * 16);
        float2 x1 = *reinterpret_cast<const float2*>(p1 + kt * 16);
        float2 x2 = *reinterpret_cast<const float2*>(p0 + kt * 16 + 8);
        float2 x3 = *reinterpret_cast<const float2*>(p1 + kt * 16 + 8);
        A[kt][0] = cvt2(x0.x, x0.y);
        A[kt][1] = cvt2(x1.x, x1.y);
        A[kt][2] = cvt2(x2.x, x2.y);
        A[kt][3] = cvt2(x3.x, x3.y);
    }
}

// hi-only packing in PAIRED fragment layout:
// block(kt, ntp) = 512B; thread th holds 16B = frags of nt=2*ntp and nt=2*ntp+1
__device__ __forceinline__ void pack_tile_hi(char* dh, const float* __restrict__ w,
                                             int KT, int tid) {
    for (int e = tid; e < KT * 4 * 32; e += THR) {
        int kt = e >> 7, rem = e & 127, ntp = rem >> 5, th = rem & 31;
        int tg = th & 3, gn = th >> 2;
        int k0 = kt * 16 + tg * 2;
        uint32_t v[4];
#pragma unroll
        for (int h = 0; h < 2; h++) {
            int n = (ntp * 2 + h) * 8 + gn;
            v[2 * h]     = cvt2(w[k0 * 64 + n],       w[(k0 + 1) * 64 + n]);
            v[2 * h + 1] = cvt2(w[(k0 + 8) * 64 + n], w[(k0 + 9) * 64 + n]);
        }
        *reinterpret_cast<uint4*>(dh + (kt * 4 + ntp) * 512 + th * 16) =
            make_uint4(v[0], v[1], v[2], v[3]);
    }
}

// ===================== HMMA MLP kernel: M=16, single-pass bf16, paired LDS =====================
__global__ void __launch_bounds__(THR, 2) mlp_mma_kernel(
    const int* __restrict__ nodes_v,
    const int* __restrict__ neigh_u, const int* __restrict__ neigh_r,
    const float* __restrict__ embed_u, const float* __restrict__ embed_i,
    const float* __restrict__ embed_r,
    const float* __restrict__ gv_w1, const float* __restrict__ gv_b1,
    const float* __restrict__ gv_w2, const float* __restrict__ gv_b2,
    const float* __restrict__ gv_w3, const float* __restrict__ gv_b3,
    const float* __restrict__ att_w1, const float* __restrict__ att_b1,
    const float* __restrict__ att_w2, const float* __restrict__ att_b2,
    const float* __restrict__ att_w3, const float* __restrict__ att_b3) {
    extern __shared__ char smem[];
    float* smf = reinterpret_cast<float*>(smem + FBASE);
    int tid = threadIdx.x;

    pack_tile_hi(smem + L_GV1, gv_w1, 4, tid);     // pt half rows 0..63
    pack_tile_hi(smem + L_GV2, gv_w2, 4, tid);
    pack_tile_hi(smem + L_GV3, gv_w3, 4, tid);
    pack_tile_hi(smem + L_ATT1, att_w1, 8, tid);   // full K=128
    pack_tile_hi(smem + L_ATT2, att_w2, 4, tid);
    if (tid < 64) {
        smf[F_BG1 + tid] = gv_b1[tid];
        smf[F_BG2 + tid] = gv_b2[tid];
        smf[F_BG3 + tid] = gv_b3[tid];
        smf[F_BA1 + tid] = att_b1[tid];
        smf[F_BA2 + tid] = att_b2[tid];
        smf[F_W3 + tid]  = att_w3[tid];
    }
    for (int e = tid; e < 320; e += THR) {
        int r = e >> 6, j = e & 63;
        float s = 0.f;
#pragma unroll 8
        for (int k = 0; k < 64; k++) s += embed_r[r * 64 + k] * gv_w1[(64 + k) * 64 + j];
        smf[F_ER + e] = s;
    }
    if (tid == 0) smf[F_BA3] = att_b3[0];
    __syncthreads();

    const char* ws = smem;
    int lane = tid & 31;
    int tig = lane & 3, gid = lane >> 2;
    int gw = blockIdx.x * (THR / 32) + (tid >> 5);
    int stride = gridDim.x * (THR / 32);
    int lb = lane * 16;

    uint32_t Ahi[4][4];
    float D[8][4];

    for (int t = gw; t < NT16; t += stride) {
        int grow0 = t * 16 + gid, grow1 = grow0 + 8;
        int nu0 = neigh_u[grow0], nu1 = neigh_u[grow1];
        int nr0 = neigh_r[grow0], nr1 = neigh_r[grow1];
        int b0 = (int)((unsigned)grow0 / 50u), b1 = (int)((unsigned)grow1 / 50u);

        gather_bf16(embed_u + (size_t)nu0 * 64 + 2 * tig,
                    embed_u + (size_t)nu1 * 64 + 2 * tig, Ahi);

        // L1: gv1(pt half) + er_proj + bg1, relu
        run_1p(ws + L_GV1 + lb, Ahi, D);
        epilogue<true, true, false>(D, Ahi, smf + F_BG1,
                                    smf + F_ER + nr0 * 64, smf + F_ER + nr1 * 64,
                                    nullptr, nullptr, tig);
        // L2: gv2 + bg2, relu
        run_1p(ws + L_GV2 + lb, Ahi, D);
        epilogue<true, false, false>(D, Ahi, smf + F_BG2,
                                     nullptr, nullptr, nullptr, nullptr, tig);
        // L3: gv3 + bg3 -> fjt (gmem) + A
        run_1p(ws + L_GV3 + lb, Ahi, D);
        epilogue<false, false, true>(D, Ahi, smf + F_BG3,
                                     nullptr, nullptr,
                                     g_fjt + (size_t)grow0 * 64, g_fjt + (size_t)grow1 * 64, tig);

        // q fragments (mostly-broadcast gather, cheap)
        uint32_t Aq[4][4];
        gather_bf16(embed_i + (size_t)nodes_v[b0] * 64 + 2 * tig,
                    embed_i + (size_t)nodes_v[b1] * 64 + 2 * tig, Aq);

        // L4: att1 K=128 single-pass
        run_att1(ws + L_ATT1 + lb, Ahi, Aq, D);
        epilogue<true, false, false>(D, Ahi, smf + F_BA1,
                                     nullptr, nullptr, nullptr, nullptr, tig);
        // L5: att2 single-pass + score dot
        run_1p(ws + L_ATT2 + lb, Ahi, D);
        {
            float s0 = 0.f, s1 = 0.f;
            float ba3v = smf[F_BA3];
#pragma unroll
            for (int nt = 0; nt < 8; nt++) {
                int col = nt * 8 + 2 * tig;
                float2 bc = *reinterpret_cast<const float2*>(smf + F_BA2 + col);
                float2 wc = *reinterpret_cast<const float2*>(smf + F_W3 + col);
                s0 += fmaxf(D[nt][0] + bc.x, 0.f) * wc.x + fmaxf(D[nt][1] + bc.y, 0.f) * wc.y;
                s1 += fmaxf(D[nt][2] + bc.x, 0.f) * wc.x + fmaxf(D[nt][3] + bc.y, 0.f) * wc.y;
            }
            s0 += __shfl_xor_sync(0xffffffffu, s0, 1);
            s0 += __shfl_xor_sync(0xffffffffu, s0, 2);
            s1 += __shfl_xor_sync(0xffffffffu, s1, 1);
            s1 += __shfl_xor_sync(0xffffffffu, s1, 2);
            if (tig == 0) {
                g_scores[grow0] = s0 + ba3v;
                g_scores[grow1] = s1 + ba3v;
            }
        }
    }
}

// ===================== agg kernel =====================
__global__ void __launch_bounds__(256) agg_kernel(
    const int* __restrict__ nodes_v, const float* __restrict__ embed_i) {
    __shared__ float mus[8][64];
    int tid = threadIdx.x;
    int warp = tid >> 5, lane = tid & 31;
    int b = blockIdx.x * 8 + warp;

    float s0 = (lane < LL) ? g_scores[b * LL + lane] : -1e30f;
    float s1 = (lane + 32 < LL) ? g_scores[b * LL + lane + 32] : -1e30f;
    float mx = fmaxf(s0, s1);
#pragma unroll
    for (int o = 16; o > 0; o >>= 1) mx = fmaxf(mx, __shfl_xor_sync(0xffffffffu, mx, o));
    float e0 = (lane < LL) ? __expf(s0 - mx) : 0.f;
    float e1 = (lane + 32 < LL) ? __expf(s1 - mx) : 0.f;
    float den = e0 + e1;
#pragma unroll
    for (int o = 16; o > 0; o >>= 1) den += __shfl_xor_sync(0xffffffffu, den, o);
    mus[warp][lane] = e0;
    mus[warp][lane + 32] = e1;
    __syncwarp();

    float a0 = 0.f, a1 = 0.f;
    const float* fb = g_fjt + (size_t)b * LL * 64 + 2 * lane;
#pragma unroll 10
    for (int l = 0; l < LL; l++) {
        float m = mus[warp][l];
        float2 v = *reinterpret_cast<const float2*>(fb + l * 64);
        a0 += m * v.x;
        a1 += m * v.y;
    }
    float inv = 1.f / den;
    float* zb = g_zq + (size_t)b * 128;
    *reinterpret_cast<float2*>(zb + 2 * lane) = make_float2(a0 * inv, a1 * inv);
    float2 qv = *reinterpret_cast<const float2*>(embed_i + (size_t)nodes_v[b] * 64 + 2 * lane);
    *reinterpret_cast<float2*>(zb + 64 + 2 * lane) = qv;
}

// ===================== mlp2 kernel =====================
__global__ void __launch_bounds__(256) mlp2_kernel(
    const float* __restrict__ wr1_w, const float* __restrict__ wr1_b,
    const float* __restrict__ wr2_w, const float* __restrict__ wr2_b,
    float* __restrict__ out) {
    __shared__ float w1s[128 * 64];
    __shared__ float w2s[64 * 64];
    __shared__ float b1s[64], b2s[64];
    __shared__ float zqs[8][128];
    __shared__ float zzs[8][64];

    int tid = threadIdx.x;
    int warp = tid >> 5, lane = tid & 31;

    {
        const float4* s1 = reinterpret_cast<const float4*>(wr1_w);
        float4* d1 = reinterpret_cast<float4*>(w1s);
        for (int e = tid; e < 128 * 16; e += 256) d1[e] = s1[e];
        const float4* s2 = reinterpret_cast<const float4*>(wr2_w);
        float4* d2 = reinterpret_cast<float4*>(w2s);
        for (int e = tid; e < 64 * 16; e += 256) d2[e] = s2[e];
        if (tid < 64) { b1s[tid] = wr1_b[tid]; b2s[tid] = wr2_b[tid]; }
    }
    __syncthreads();

#pragma unroll
    for (int i = 0; i < 2; i++) {
        int b = blockIdx.x * 16 + warp * 2 + i;

        *reinterpret_cast<float4*>(&zqs[warp][lane * 4]) =
            *reinterpret_cast<const float4*>(g_zq + (size_t)b * 128 + lane * 4);
        __syncwarp();

        float o0 = b1s[lane], o1 = b1s[lane + 32];
#pragma unroll 16
        for (int k = 0; k < 128; k++) {
            float v = zqs[warp][k];
            o0 += v * w1s[k * 64 + lane];
            o1 += v * w1s[k * 64 + lane + 32];
        }
        zzs[warp][lane]      = fmaxf(o0, 0.f);
        zzs[warp][lane + 32] = fmaxf(o1, 0.f);
        __syncwarp();

        float p0 = b2s[lane], p1 = b2s[lane + 32];
#pragma unroll 16
        for (int k = 0; k < 64; k++) {
            float v = zzs[warp][k];
            p0 += v * w2s[k * 64 + lane];
            p1 += v * w2s[k * 64 + lane + 32];
        }
        out[b * 64 + lane]      = fmaxf(p0, 0.f);
        out[b * 64 + lane + 32] = fmaxf(p1, 0.f);
        __syncwarp();
    }
}

extern "C" void kernel_launch(void* const* d_in, const int* in_sizes, int n_in,
                              void* d_out, int out_size) {
    const int*   nodes_v = (const int*)d_in[0];
    const int*   neigh_u = (const int*)d_in[1];
    const int*   neigh_r = (const int*)d_in[2];
    const float* embed_u = (const float*)d_in[3];
    const float* embed_i = (const float*)d_in[4];
    const float* embed_r = (const float*)d_in[5];
    const float* gv_w1  = (const float*)d_in[6];
    const float* gv_b1  = (const float*)d_in[7];
    const float* gv_w2  = (const float*)d_in[8];
    const float* gv_b2  = (const float*)d_in[9];
    const float* gv_w3  = (const float*)d_in[10];
    const float* gv_b3  = (const float*)d_in[11];
    const float* att_w1 = (const float*)d_in[12];
    const float* att_b1 = (const float*)d_in[13];
    const float* att_w2 = (const float*)d_in[14];
    const float* att_b2 = (const float*)d_in[15];
    const float* att_w3 = (const float*)d_in[16];
    const float* att_b3 = (const float*)d_in[17];
    const float* wr1_w  = (const float*)d_in[18];
    const float* wr1_b  = (const float*)d_in[19];
    const float* wr2_w  = (const float*)d_in[20];
    const float* wr2_b  = (const float*)d_in[21];
    float* out = (float*)d_out;

    cudaFuncSetAttribute(mlp_mma_kernel, cudaFuncAttributeMaxDynamicSharedMemorySize, SMEM_SZ);

    int smCount = 148;
    cudaDeviceGetAttribute(&smCount, cudaDevAttrMultiProcessorCount, 0);

    mlp_mma_kernel<<<2 * smCount, THR, SMEM_SZ>>>(
        nodes_v, neigh_u, neigh_r, embed_u, embed_i, embed_r,
        gv_w1, gv_b1, gv_w2, gv_b2, gv_w3, gv_b3,
        att_w1, att_b1, att_w2, att_b2, att_w3, att_b3);

    agg_kernel<<<BB / 8, 256>>>(nodes_v, embed_i);

    mlp2_kernel<<<BB / 16, 256>>>(wr1_w, wr1_b, wr2_w, wr2_b, out);
}

// round 17
// speedup vs baseline: 1.2005x; 1.0362x over previous
#include <cuda_runtime.h>
#include <cuda_bf16.h>
#include <cstdint>
#include <math.h>

#define BB 4096
#define LL 50
#define DD 64

constexpr int ROWS_TOT = BB * LL;        // 204800
constexpr int NT32     = ROWS_TOT / 32;  // 6400 tiles of 32 rows
constexpr int THR      = 256;

// ---- mlp smem layout (bytes): hi-only PAIRED-fragment tiles ----
constexpr int L_GV1  = 0;                // 8192
constexpr int L_GV2  = 8192;
constexpr int L_GV3  = 16384;
constexpr int L_ATT1 = 24576;            // 16384 (K=128; chunk2 at +8192)
constexpr int L_ATT2 = 40960;            // 8192
constexpr int FBASE  = 49152;
constexpr int F_BG1 = 0, F_BG2 = 64, F_BG3 = 128, F_BA1 = 192, F_BA2 = 256;
constexpr int F_W3 = 320, F_BA3 = 384, F_ER = 448;
constexpr int SMEM_SZ = FBASE + 768 * 4;   // 52224 B

// device scratch
__device__ float g_scores[ROWS_TOT];
__device__ float g_fjt[ROWS_TOT * DD];
__device__ float g_zq[BB * 128];
__device__ int   g_task;

// ===================== helpers =====================
__device__ __forceinline__ uint32_t cvt2(float v_lo, float v_hi) {
    uint32_t r;
    asm("cvt.rn.bf16x2.f32 %0, %1, %2;" : "=r"(r) : "f"(v_hi), "f"(v_lo));
    return r;
}
__device__ __forceinline__ void mma(float* d, const uint32_t* a, uint32_t b0, uint32_t b1) {
    asm volatile(
        "mma.sync.aligned.m16n8k16.row.col.f32.bf16.bf16.f32 "
        "{%0,%1,%2,%3}, {%4,%5,%6,%7}, {%8,%9}, {%0,%1,%2,%3};"
        : "+f"(d[0]), "+f"(d[1]), "+f"(d[2]), "+f"(d[3])
        : "r"(a[0]), "r"(a[1]), "r"(a[2]), "r"(a[3]), "r"(b0), "r"(b1));
}

// K=64 layer over a 32-row tile (2 subtiles share each weight fragment).
// kt-outer: each LDS.128 weight quad feeds 2 MMAs x 2 subtiles.
template<bool INIT>
__device__ __forceinline__ void run_layer32(const char* base,
        const uint32_t (&A)[2][4][4], float (&D)[2][8][4]) {
    if (INIT) {
#pragma unroll
        for (int s = 0; s < 2; s++)
#pragma unroll
            for (int nt = 0; nt < 8; nt++) {
                D[s][nt][0] = 0.f; D[s][nt][1] = 0.f;
                D[s][nt][2] = 0.f; D[s][nt][3] = 0.f;
            }
    }
#pragma unroll
    for (int kt = 0; kt < 4; kt++) {
#pragma unroll
        for (int pp = 0; pp < 2; pp++) {
            uint4 b0 = *reinterpret_cast<const uint4*>(base + (kt * 4 + 2 * pp) * 512);
            uint4 b1 = *reinterpret_cast<const uint4*>(base + (kt * 4 + 2 * pp + 1) * 512);
#pragma unroll
            for (int s = 0; s < 2; s++) {
                mma(D[s][4 * pp + 0], A[s][kt], b0.x, b0.y);
                mma(D[s][4 * pp + 1], A[s][kt], b0.z, b0.w);
                mma(D[s][4 * pp + 2], A[s][kt], b1.x, b1.y);
                mma(D[s][4 * pp + 3], A[s][kt], b1.z, b1.w);
            }
        }
    }
}

// bias (+extra) (+relu) (+gmem store), D -> next A frags (bf16), one subtile
template<bool RELU, bool EX, bool SG>
__device__ __forceinline__ void epilogue(float (&D)[8][4], uint32_t (&A)[4][4],
        const float* bias, const float* e0, const float* e1, float* g0, float* g1, int tig) {
#pragma unroll
    for (int nt = 0; nt < 8; nt++) {
        int col = nt * 8 + 2 * tig;
        float2 bc = *reinterpret_cast<const float2*>(bias + col);
        float v0 = D[nt][0] + bc.x, v1 = D[nt][1] + bc.y;
        float v2 = D[nt][2] + bc.x, v3 = D[nt][3] + bc.y;
        if (EX) {
            float2 ea = *reinterpret_cast<const float2*>(e0 + col);
            float2 eb = *reinterpret_cast<const float2*>(e1 + col);
            v0 += ea.x; v1 += ea.y; v2 += eb.x; v3 += eb.y;
        }
        if (RELU) {
            v0 = fmaxf(v0, 0.f); v1 = fmaxf(v1, 0.f);
            v2 = fmaxf(v2, 0.f); v3 = fmaxf(v3, 0.f);
        }
        if (SG) {
            *reinterpret_cast<float2*>(g0 + col) = make_float2(v0, v1);
            *reinterpret_cast<float2*>(g1 + col) = make_float2(v2, v3);
        }
        int kt = nt >> 1, ix = (nt & 1) * 2;
        A[kt][ix]     = cvt2(v0, v1);
        A[kt][ix + 1] = cvt2(v2, v3);
    }
}

__device__ __forceinline__ void gather_bf16(const float* p0, const float* p1,
        uint32_t (&A)[4][4]) {
#pragma unroll
    for (int kt = 0; kt < 4; kt++) {
        float2 x0 = *reinterpret_cast<const float2*>(p0 + kt * 16);
        float2 x1 = *reinterpret_cast<const float2*>(p1 + kt * 16);
        float2 x2 = *reinterpret_cast<const float2*>(p0 + kt * 16 + 8);
        float2 x3 = *reinterpret_cast<const float2*>(p1 + kt * 16 + 8);
        A[kt][0] = cvt2(x0.x, x0.y);
        A[kt][1] = cvt2(x1.x, x1.y);
        A[kt][2] = cvt2(x2.x, x2.y);
        A[kt][3] = cvt2(x3.x, x3.y);
    }
}

// hi-only packing, PAIRED layout: block(kt,ntp)=512B, thread th holds 16B
__device__ __forceinline__ void pack_tile_hi(char* dh, const float* __restrict__ w,
                                             int KT, int tid) {
    for (int e = tid; e < KT * 4 * 32; e += THR) {
        int kt = e >> 7, rem = e & 127, ntp = rem >> 5, th = rem & 31;
        int tg = th & 3, gn = th >> 2;
        int k0 = kt * 16 + tg * 2;
        uint32_t v[4];
#pragma unroll
        for (int h = 0; h < 2; h++) {
            int n = (ntp * 2 + h) * 8 + gn;
            v[2 * h]     = cvt2(w[k0 * 64 + n],       w[(k0 + 1) * 64 + n]);
            v[2 * h + 1] = cvt2(w[(k0 + 8) * 64 + n], w[(k0 + 9) * 64 + n]);
        }
        *reinterpret_cast<uint4*>(dh + (kt * 4 + ntp) * 512 + th * 16) =
            make_uint4(v[0], v[1], v[2], v[3]);
    }
}

// ===================== HMMA MLP kernel: M=32, shared-weight subtiles =====================
__global__ void __launch_bounds__(THR, 2) mlp_mma_kernel(
    const int* __restrict__ nodes_v,
    const int* __restrict__ neigh_u, const int* __restrict__ neigh_r,
    const float* __restrict__ embed_u, const float* __restrict__ embed_i,
    const float* __restrict__ embed_r,
    const float* __restrict__ gv_w1, const float* __restrict__ gv_b1,
    const float* __restrict__ gv_w2, const float* __restrict__ gv_b2,
    const float* __restrict__ gv_w3, const float* __restrict__ gv_b3,
    const float* __restrict__ att_w1, const float* __restrict__ att_b1,
    const float* __restrict__ att_w2, const float* __restrict__ att_b2,
    const float* __restrict__ att_w3, const float* __restrict__ att_b3) {
    extern __shared__ char smem[];
    float* smf = reinterpret_cast<float*>(smem + FBASE);
    int tid = threadIdx.x;

    pack_tile_hi(smem + L_GV1, gv_w1, 4, tid);     // pt half rows 0..63
    pack_tile_hi(smem + L_GV2, gv_w2, 4, tid);
    pack_tile_hi(smem + L_GV3, gv_w3, 4, tid);
    pack_tile_hi(smem + L_ATT1, att_w1, 8, tid);   // full K=128
    pack_tile_hi(smem + L_ATT2, att_w2, 4, tid);
    if (tid < 64) {
        smf[F_BG1 + tid] = gv_b1[tid];
        smf[F_BG2 + tid] = gv_b2[tid];
        smf[F_BG3 + tid] = gv_b3[tid];
        smf[F_BA1 + tid] = att_b1[tid];
        smf[F_BA2 + tid] = att_b2[tid];
        smf[F_W3 + tid]  = att_w3[tid];
    }
    for (int e = tid; e < 320; e += THR) {
        int r = e >> 6, j = e & 63;
        float s = 0.f;
#pragma unroll 8
        for (int k = 0; k < 64; k++) s += embed_r[r * 64 + k] * gv_w1[(64 + k) * 64 + j];
        smf[F_ER + e] = s;
    }
    if (tid == 0) smf[F_BA3] = att_b3[0];
    __syncthreads();

    const char* ws = smem;
    int lane = tid & 31;
    int tig = lane & 3, gid = lane >> 2;
    int lb = lane * 16;

    uint32_t A[2][4][4];
    float D[2][8][4];

    for (;;) {
        int t;
        if (lane == 0) t = atomicAdd(&g_task, 1);
        t = __shfl_sync(0xffffffffu, t, 0);
        if (t >= NT32) break;

        int base_row = t * 32;
        int grow[2][2];
        int nr[2][2];
#pragma unroll
        for (int s = 0; s < 2; s++) {
            grow[s][0] = base_row + 16 * s + gid;
            grow[s][1] = grow[s][0] + 8;
            nr[s][0] = neigh_r[grow[s][0]];
            nr[s][1] = neigh_r[grow[s][1]];
        }

        // gather pt rows
#pragma unroll
        for (int s = 0; s < 2; s++) {
            int nu0 = neigh_u[grow[s][0]], nu1 = neigh_u[grow[s][1]];
            gather_bf16(embed_u + (size_t)nu0 * 64 + 2 * tig,
                        embed_u + (size_t)nu1 * 64 + 2 * tig, A[s]);
        }

        // L1: gv1(pt half) + er_proj + bg1, relu
        run_layer32<true>(ws + L_GV1 + lb, A, D);
#pragma unroll
        for (int s = 0; s < 2; s++)
            epilogue<true, true, false>(D[s], A[s], smf + F_BG1,
                smf + F_ER + nr[s][0] * 64, smf + F_ER + nr[s][1] * 64,
                nullptr, nullptr, tig);

        // L2: gv2 + bg2, relu
        run_layer32<true>(ws + L_GV2 + lb, A, D);
#pragma unroll
        for (int s = 0; s < 2; s++)
            epilogue<true, false, false>(D[s], A[s], smf + F_BG2,
                nullptr, nullptr, nullptr, nullptr, tig);

        // L3: gv3 + bg3 -> fjt (gmem) + A
        run_layer32<true>(ws + L_GV3 + lb, A, D);
#pragma unroll
        for (int s = 0; s < 2; s++)
            epilogue<false, false, true>(D[s], A[s], smf + F_BG3,
                nullptr, nullptr,
                g_fjt + (size_t)grow[s][0] * 64, g_fjt + (size_t)grow[s][1] * 64, tig);

        // L4 att1 chunk1: fjt frags vs att_w1 rows 0..63 (accumulate into D)
        run_layer32<true>(ws + L_ATT1 + lb, A, D);

        // overwrite A with q frags (fjt frags dead after L3 store)
#pragma unroll
        for (int s = 0; s < 2; s++) {
            int b0 = (int)((unsigned)grow[s][0] / 50u);
            int b1 = (int)((unsigned)grow[s][1] / 50u);
            gather_bf16(embed_i + (size_t)nodes_v[b0] * 64 + 2 * tig,
                        embed_i + (size_t)nodes_v[b1] * 64 + 2 * tig, A[s]);
        }

        // L4 att1 chunk2: q frags vs att_w1 rows 64..127 (no re-init)
        run_layer32<false>(ws + L_ATT1 + 8192 + lb, A, D);
#pragma unroll
        for (int s = 0; s < 2; s++)
            epilogue<true, false, false>(D[s], A[s], smf + F_BA1,
                nullptr, nullptr, nullptr, nullptr, tig);

        // L5: att2 + score dot
        run_layer32<true>(ws + L_ATT2 + lb, A, D);
        {
            float ba3v = smf[F_BA3];
#pragma unroll
            for (int s = 0; s < 2; s++) {
                float s0 = 0.f, s1 = 0.f;
#pragma unroll
                for (int nt = 0; nt < 8; nt++) {
                    int col = nt * 8 + 2 * tig;
                    float2 bc = *reinterpret_cast<const float2*>(smf + F_BA2 + col);
                    float2 wc = *reinterpret_cast<const float2*>(smf + F_W3 + col);
                    s0 += fmaxf(D[s][nt][0] + bc.x, 0.f) * wc.x + fmaxf(D[s][nt][1] + bc.y, 0.f) * wc.y;
                    s1 += fmaxf(D[s][nt][2] + bc.x, 0.f) * wc.x + fmaxf(D[s][nt][3] + bc.y, 0.f) * wc.y;
                }
                s0 += __shfl_xor_sync(0xffffffffu, s0, 1);
                s0 += __shfl_xor_sync(0xffffffffu, s0, 2);
                s1 += __shfl_xor_sync(0xffffffffu, s1, 1);
                s1 += __shfl_xor_sync(0xffffffffu, s1, 2);
                if (tig == 0) {
                    g_scores[grow[s][0]] = s0 + ba3v;
                    g_scores[grow[s][1]] = s1 + ba3v;
                }
            }
        }
    }
}

// ===================== agg kernel =====================
__global__ void __launch_bounds__(256) agg_kernel(
    const int* __restrict__ nodes_v, const float* __restrict__ embed_i) {
    __shared__ float mus[8][64];
    int tid = threadIdx.x;
    int warp = tid >> 5, lane = tid & 31;
    int b = blockIdx.x * 8 + warp;

    float s0 = (lane < LL) ? g_scores[b * LL + lane] : -1e30f;
    float s1 = (lane + 32 < LL) ? g_scores[b * LL + lane + 32] : -1e30f;
    float mx = fmaxf(s0, s1);
#pragma unroll
    for (int o = 16; o > 0; o >>= 1) mx = fmaxf(mx, __shfl_xor_sync(0xffffffffu, mx, o));
    float e0 = (lane < LL) ? __expf(s0 - mx) : 0.f;
    float e1 = (lane + 32 < LL) ? __expf(s1 - mx) : 0.f;
    float den = e0 + e1;
#pragma unroll
    for (int o = 16; o > 0; o >>= 1) den += __shfl_xor_sync(0xffffffffu, den, o);
    mus[warp][lane] = e0;
    mus[warp][lane + 32] = e1;
    __syncwarp();

    float a0 = 0.f, a1 = 0.f;
    const float* fb = g_fjt + (size_t)b * LL * 64 + 2 * lane;
#pragma unroll 10
    for (int l = 0; l < LL; l++) {
        float m = mus[warp][l];
        float2 v = *reinterpret_cast<const float2*>(fb + l * 64);
        a0 += m * v.x;
        a1 += m * v.y;
    }
    float inv = 1.f / den;
    float* zb = g_zq + (size_t)b * 128;
    *reinterpret_cast<float2*>(zb + 2 * lane) = make_float2(a0 * inv, a1 * inv);
    float2 qv = *reinterpret_cast<const float2*>(embed_i + (size_t)nodes_v[b] * 64 + 2 * lane);
    *reinterpret_cast<float2*>(zb + 64 + 2 * lane) = qv;
}

// ===================== mlp2 kernel =====================
__global__ void __launch_bounds__(256) mlp2_kernel(
    const float* __restrict__ wr1_w, const float* __restrict__ wr1_b,
    const float* __restrict__ wr2_w, const float* __restrict__ wr2_b,
    float* __restrict__ out) {
    __shared__ float w1s[128 * 64];
    __shared__ float w2s[64 * 64];
    __shared__ float b1s[64], b2s[64];
    __shared__ float zqs[8][128];
    __shared__ float zzs[8][64];

    int tid = threadIdx.x;
    int warp = tid >> 5, lane = tid & 31;

    {
        const float4* s1 = reinterpret_cast<const float4*>(wr1_w);
        float4* d1 = reinterpret_cast<float4*>(w1s);
        for (int e = tid; e < 128 * 16; e += 256) d1[e] = s1[e];
        const float4* s2 = reinterpret_cast<const float4*>(wr2_w);
        float4* d2 = reinterpret_cast<float4*>(w2s);
        for (int e = tid; e < 64 * 16; e += 256) d2[e] = s2[e];
        if (tid < 64) { b1s[tid] = wr1_b[tid]; b2s[tid] = wr2_b[tid]; }
    }
    __syncthreads();

#pragma unroll
    for (int i = 0; i < 2; i++) {
        int b = blockIdx.x * 16 + warp * 2 + i;

        *reinterpret_cast<float4*>(&zqs[warp][lane * 4]) =
            *reinterpret_cast<const float4*>(g_zq + (size_t)b * 128 + lane * 4);
        __syncwarp();

        float o0 = b1s[lane], o1 = b1s[lane + 32];
#pragma unroll 16
        for (int k = 0; k < 128; k++) {
            float v = zqs[warp][k];
            o0 += v * w1s[k * 64 + lane];
            o1 += v * w1s[k * 64 + lane + 32];
        }
        zzs[warp][lane]      = fmaxf(o0, 0.f);
        zzs[warp][lane + 32] = fmaxf(o1, 0.f);
        __syncwarp();

        float p0 = b2s[lane], p1 = b2s[lane + 32];
#pragma unroll 16
        for (int k = 0; k < 64; k++) {
            float v = zzs[warp][k];
            p0 += v * w2s[k * 64 + lane];
            p1 += v * w2s[k * 64 + lane + 32];
        }
        out[b * 64 + lane]      = fmaxf(p0, 0.f);
        out[b * 64 + lane + 32] = fmaxf(p1, 0.f);
        __syncwarp();
    }
}

extern "C" void kernel_launch(void* const* d_in, const int* in_sizes, int n_in,
                              void* d_out, int out_size) {
    const int*   nodes_v = (const int*)d_in[0];
    const int*   neigh_u = (const int*)d_in[1];
    const int*   neigh_r = (const int*)d_in[2];
    const float* embed_u = (const float*)d_in[3];
    const float* embed_i = (const float*)d_in[4];
    const float* embed_r = (const float*)d_in[5];
    const float* gv_w1  = (const float*)d_in[6];
    const float* gv_b1  = (const float*)d_in[7];
    const float* gv_w2  = (const float*)d_in[8];
    const float* gv_b2  = (const float*)d_in[9];
    const float* gv_w3  = (const float*)d_in[10];
    const float* gv_b3  = (const float*)d_in[11];
    const float* att_w1 = (const float*)d_in[12];
    const float* att_b1 = (const float*)d_in[13];
    const float* att_w2 = (const float*)d_in[14];
    const float* att_b2 = (const float*)d_in[15];
    const float* att_w3 = (const float*)d_in[16];
    const float* att_b3 = (const float*)d_in[17];
    const float* wr1_w  = (const float*)d_in[18];
    const float* wr1_b  = (const float*)d_in[19];
    const float* wr2_w  = (const float*)d_in[20];
    const float* wr2_b  = (const float*)d_in[21];
    float* out = (float*)d_out;

    cudaFuncSetAttribute(mlp_mma_kernel, cudaFuncAttributeMaxDynamicSharedMemorySize, SMEM_SZ);

    int smCount = 148;
    cudaDeviceGetAttribute(&smCount, cudaDevAttrMultiProcessorCount, 0);

    void* task_ptr = nullptr;
    cudaGetSymbolAddress(&task_ptr, g_task);
    cudaMemsetAsync(task_ptr, 0, sizeof(int));

    mlp_mma_kernel<<<2 * smCount, THR, SMEM_SZ>>>(
        nodes_v, neigh_u, neigh_r, embed_u, embed_i, embed_r,
        gv_w1, gv_b1, gv_w2, gv_b2, gv_w3, gv_b3,
        att_w1, att_b1, att_w2, att_b2, att_w3, att_b3);

    agg_kernel<<<BB / 8, 256>>>(nodes_v, embed_i);

    mlp2_kernel<<<BB / 16, 256>>>(wr1_w, wr1_b, wr2_w, wr2_b, out);
}